// round 12
// baseline (speedup 1.0000x reference)
#include <cuda_runtime.h>
#include <cuda_fp16.h>
#include <cstdint>

#define BATCH 4
#define SEQ   4096
#define EMB   1024
#define DD    128
#define BS    (BATCH * SEQ)

// Scratch (allocation-free rule: __device__ globals).
__device__ __half g_xh[(size_t)BS * EMB];
__device__ __half g_xl[(size_t)BS * EMB];
__device__ __half g_wh[3 * EMB * DD];
__device__ __half g_qh[(size_t)BS * DD];   // pre-scaled by qsc (fp16)
__device__ __half g_kh[(size_t)BS * DD];
__device__ __half g_vh[(size_t)BS * DD];
// Split-KV partials: [batch 4][pair 16][slot 2][row 128][d 128] and l.
__device__ float g_Opart[4 * 16 * 2 * 128 * 128];
__device__ float g_lpart[4 * 16 * 2 * 128];

// ===========================================================================
// Helpers — baseline sm_100 PTX (ldmatrix + mma.sync fp16 + cp.async).
// ===========================================================================
__device__ __forceinline__ uint32_t smem_u32(const void* p) {
    uint32_t a;
    asm("{ .reg .u64 t; cvta.to.shared.u64 t, %1; cvt.u32.u64 %0, t; }"
        : "=r"(a) : "l"(p));
    return a;
}
// pack two fp32 -> f16x2 (first arg -> low half)
__device__ __forceinline__ uint32_t pack2h(float lo, float hi) {
    uint32_t r;
    asm("cvt.rn.f16x2.f32 %0, %1, %2;" : "=r"(r) : "f"(hi), "f"(lo));
    return r;
}
__device__ __forceinline__ float h_lo(uint32_t u) {
    return __half2float(__ushort_as_half((unsigned short)(u & 0xFFFFu)));
}
__device__ __forceinline__ float h_hi(uint32_t u) {
    return __half2float(__ushort_as_half((unsigned short)(u >> 16)));
}
__device__ __forceinline__ float ex2(float x) {
    float r; asm("ex2.approx.f32 %0, %1;" : "=f"(r) : "f"(x)); return r;
}
__device__ __forceinline__ void cpa16(uint32_t dst, const void* src) {
    asm volatile("cp.async.cg.shared.global [%0], [%1], 16;"
        :: "r"(dst), "l"(__cvta_generic_to_global(src)) : "memory");
}
#define CP_COMMIT() asm volatile("cp.async.commit_group;" ::: "memory")
#define CP_WAIT1()  asm volatile("cp.async.wait_group 1;" ::: "memory")
#define CP_WAIT0()  asm volatile("cp.async.wait_group 0;" ::: "memory")

__device__ __forceinline__ void ldsm4(uint32_t a, uint32_t* r) {
    asm volatile("ldmatrix.sync.aligned.m8n8.x4.shared.b16 {%0,%1,%2,%3}, [%4];"
        : "=r"(r[0]), "=r"(r[1]), "=r"(r[2]), "=r"(r[3]) : "r"(a));
}
__device__ __forceinline__ void ldsm4t(uint32_t a, uint32_t* r) {
    asm volatile("ldmatrix.sync.aligned.m8n8.x4.trans.shared.b16 {%0,%1,%2,%3}, [%4];"
        : "=r"(r[0]), "=r"(r[1]), "=r"(r[2]), "=r"(r[3]) : "r"(a));
}
// D += A * B  (m16n8k16, fp16 -> f32)
__device__ __forceinline__ void mma16816(float* c, const uint32_t* a,
                                         uint32_t b0, uint32_t b1) {
    asm volatile(
        "mma.sync.aligned.m16n8k16.row.col.f32.f16.f16.f32 "
        "{%0,%1,%2,%3}, {%4,%5,%6,%7}, {%8,%9}, {%0,%1,%2,%3};"
        : "+f"(c[0]), "+f"(c[1]), "+f"(c[2]), "+f"(c[3])
        : "r"(a[0]), "r"(a[1]), "r"(a[2]), "r"(a[3]), "r"(b0), "r"(b1));
}

// ===========================================================================
// Kernel 0a: convert x (fp32) -> xh + xl (fp16 split).  8 elems/thread.
// ===========================================================================
__global__ __launch_bounds__(256) void conv_x_kernel(const float* __restrict__ x)
{
    size_t i = ((size_t)blockIdx.x * 256 + threadIdx.x) * 8;
    float4 a = *reinterpret_cast<const float4*>(x + i);
    float4 b = *reinterpret_cast<const float4*>(x + i + 4);
    uint32_t h0 = pack2h(a.x, a.y), h1 = pack2h(a.z, a.w);
    uint32_t h2 = pack2h(b.x, b.y), h3 = pack2h(b.z, b.w);
    uint32_t l0 = pack2h(a.x - h_lo(h0), a.y - h_hi(h0));
    uint32_t l1 = pack2h(a.z - h_lo(h1), a.w - h_hi(h1));
    uint32_t l2 = pack2h(b.x - h_lo(h2), b.y - h_hi(h2));
    uint32_t l3 = pack2h(b.z - h_lo(h3), b.w - h_hi(h3));
    *reinterpret_cast<uint4*>(&g_xh[i]) = make_uint4(h0, h1, h2, h3);
    *reinterpret_cast<uint4*>(&g_xl[i]) = make_uint4(l0, l1, l2, l3);
}

// ===========================================================================
// Kernel 0b: convert Wq/Wk/Wv (fp32) -> wh (fp16 single).  4 elems/thread.
// ===========================================================================
__global__ __launch_bounds__(256) void conv_w_kernel(
    const float* __restrict__ Wq, const float* __restrict__ Wk,
    const float* __restrict__ Wv)
{
    const float* W = (blockIdx.y == 0) ? Wq : (blockIdx.y == 1) ? Wk : Wv;
    size_t i = ((size_t)blockIdx.x * 256 + threadIdx.x) * 4;
    float4 v = *reinterpret_cast<const float4*>(W + i);
    uint32_t p0 = pack2h(v.x, v.y), p1 = pack2h(v.z, v.w);
    *reinterpret_cast<uint2*>(&g_wh[(size_t)blockIdx.y * EMB * DD + i]) =
        make_uint2(p0, p1);
}

// ===========================================================================
// Kernel 1: QKV projection GEMM, fp16x2 (split X only), cp.async 2-stage.
// Block 256 thr, tile M=128 N=128, K chunks of 64.  Warp tile 32M x 64N.
// grid = (128, 3).  Writes fp16 outputs (Q pre-scaled, single fp16).
// (Unchanged from the R11-passing kernel.)
// ===========================================================================
#define GEM_BUF 54272
#define G_SMEM  (2 * GEM_BUF)    // 108544

__global__ __launch_bounds__(256, 2) void qkv_gemm(void)
{
    extern __shared__ char smem[];
    const uint32_t sb = smem_u32(smem);
    const int t = threadIdx.x;
    const int w = t >> 5, l = t & 31;
    const int g = l >> 2, tig = l & 3;
    const int wM = w & 3, wN = w >> 2;
    const int m0 = blockIdx.x * 128;
    const int y  = blockIdx.y;
    const __half* ws = g_wh + (size_t)y * EMB * DD;

    float C[2][8][4];
    #pragma unroll
    for (int m = 0; m < 2; m++)
        #pragma unroll
        for (int i = 0; i < 8; i++)
            #pragma unroll
            for (int j = 0; j < 4; j++) C[m][i][j] = 0.f;

    auto issue = [&](int p, int cc) {
        const uint32_t bb = sb + p * GEM_BUF;
        const int k0 = cc * 64;
        #pragma unroll
        for (int i = 0; i < 8; i++) {
            int pid = t + i * 256;
            int op = pid >> 10, rem = pid & 1023;
            int row = rem >> 3, piece = rem & 7;
            const __half* src = (op ? g_xl : g_xh)
                + (size_t)(m0 + row) * EMB + k0 + piece * 8;
            cpa16(bb + op * 18432 + row * 144 + piece * 16, src);
        }
        #pragma unroll
        for (int i = 0; i < 4; i++) {
            int pid = t + i * 256;
            int row = pid >> 4, piece = pid & 15;
            cpa16(bb + 36864 + row * 272 + piece * 16,
                  ws + (size_t)(k0 + row) * DD + piece * 8);
        }
        CP_COMMIT();
    };

    issue(0, 0);
    issue(1, 1);

    const uint32_t xa_l = (uint32_t)(wM * 32 * 144
                        + (l & 15) * 144 + ((l >> 4) << 3) * 2);
    const uint32_t wb_l = (uint32_t)(((l & 7) + (l & 8)) * 272
                        + ((l >> 4) << 3) * 2 + wN * 128);

    for (int cc = 0; cc < 16; cc++) {
        const int p = cc & 1;
        if (cc < 15) CP_WAIT1(); else CP_WAIT0();
        __syncthreads();
        const uint32_t bb = sb + p * GEM_BUF;

        #pragma unroll
        for (int ks = 0; ks < 4; ks++) {
            uint32_t ah0[4], ah1[4], al0[4], al1[4];
            uint32_t xa = bb + xa_l + ks * 32;
            ldsm4(xa,              ah0);
            ldsm4(xa + 16 * 144,   ah1);
            ldsm4(xa + 18432,           al0);
            ldsm4(xa + 18432 + 16*144,  al1);
            #pragma unroll
            for (int np = 0; np < 4; np++) {
                uint32_t bf[4];
                ldsm4t(bb + 36864 + wb_l + ks * 4352 + np * 32, bf);
                mma16816(C[0][2*np],   ah0, bf[0], bf[1]);
                mma16816(C[0][2*np],   al0, bf[0], bf[1]);
                mma16816(C[0][2*np+1], ah0, bf[2], bf[3]);
                mma16816(C[0][2*np+1], al0, bf[2], bf[3]);
                mma16816(C[1][2*np],   ah1, bf[0], bf[1]);
                mma16816(C[1][2*np],   al1, bf[0], bf[1]);
                mma16816(C[1][2*np+1], ah1, bf[2], bf[3]);
                mma16816(C[1][2*np+1], al1, bf[2], bf[3]);
            }
        }
        __syncthreads();
        if (cc + 2 < 16) issue(p, cc + 2);
    }

    // epilogue -> fp16 global (Q pre-scaled, single fp16)
    const float qsc = 0.08838834764831845f * 1.4426950408889634f;
    #pragma unroll
    for (int m = 0; m < 2; m++) {
        const int r0 = m0 + wM * 32 + m * 16 + g;
        const int r1 = r0 + 8;
        #pragma unroll
        for (int nt = 0; nt < 8; nt++) {
            const int col = wN * 64 + nt * 8 + 2 * tig;
            float v00 = C[m][nt][0], v01 = C[m][nt][1];
            float v10 = C[m][nt][2], v11 = C[m][nt][3];
            __half* dst;
            if (y == 0) {
                v00 *= qsc; v01 *= qsc; v10 *= qsc; v11 *= qsc;
                dst = g_qh;
            } else dst = (y == 1) ? g_kh : g_vh;
            *reinterpret_cast<uint32_t*>(&dst[(size_t)r0 * DD + col]) =
                pack2h(v00, v01);
            *reinterpret_cast<uint32_t*>(&dst[(size_t)r1 * DD + col]) =
                pack2h(v10, v11);
        }
    }
}

// ===========================================================================
// Kernel 2: causal flash attention — 256 thr, 8 warps, block-wide syncs only.
// Single-term fp16 MMAs.  NEW (R12): cross-tile software pipelining — QK of
// tile i+1 is interleaved with PV of tile i in one barrier-free region; one
// __syncthreads per tile; 3-stage KV ring (PV reads buf i%3, QK reads
// (i+1)%3, prefetch i+2 lands in (i+2)%3 — all distinct mod 3).
// Q-tile 128, key-tile 64, no-max softmax, O in fp32 regs.
// Schedule: pair ip -> 2 blocks of 33 units; grid 128.
// ===========================================================================
#define FQ      0
#define FKV     34816
#define KVBUF   34816
#define FA_SMEM (FKV + 3 * KVBUF)   // 139264

__global__ __launch_bounds__(256, 1) void flash_attn(float* __restrict__ out)
{
    extern __shared__ char smem[];
    const uint32_t sb = smem_u32(smem);
    const int t = threadIdx.x;
    const int w = t >> 5, l = t & 31;
    const int g = l >> 2, tig = l & 3;

    const int bid  = blockIdx.x;
    const int b    = bid >> 5;
    const int rem  = bid & 31;
    const int ip   = rem >> 1;
    const int half = rem & 1;

    const uint32_t qa_lane = (uint32_t)((16 * w + (l & 15)) * 272 + ((l >> 4) << 3) * 2);
    const uint32_t kb_lane = (uint32_t)(((l & 7) + ((l >> 4) << 3)) * 272 + (l & 8) * 2);
    const uint32_t vb_lane = (uint32_t)(((l & 7) + (l & 8)) * 272 + ((l >> 4) << 3) * 2);

    float S[8][4];
    float O[16][4];

    auto issue_kv = [&](int buf, int kt) {
        const int k0 = kt * 64;
        const uint32_t bb = sb + FKV + (uint32_t)buf * KVBUF;
        #pragma unroll
        for (int i = 0; i < 8; i++) {
            int pid = t + i * 256;
            int arr = pid >> 10, r2 = pid & 1023;
            int row = r2 >> 4, piece = r2 & 15;
            const __half* src = (arr ? g_vh : g_kh)
                + ((size_t)b * SEQ + k0 + row) * DD + piece * 8;
            cpa16(bb + arr * 17408 + row * 272 + piece * 16, src);
        }
        CP_COMMIT();
    };
    // one K-step of QK: S += Q[:, ks] * K[:, ks]^T from buffer base kbn
    auto qk_step = [&](uint32_t kbn, int ks) {
        uint32_t ah[4];
        ldsm4(sb + FQ + qa_lane + ks * 32, ah);
        #pragma unroll
        for (int np = 0; np < 4; np++) {
            uint32_t bk[4];
            ldsm4(kbn + np * 4352 + ks * 32, bk);
            mma16816(S[2*np],   ah, bk[0], bk[1]);
            mma16816(S[2*np+1], ah, bk[2], bk[3]);
        }
    };
    // one k-chunk of PV: O += P[:, kk] * V[kk, :]
    auto pv_step = [&](uint32_t vbb, const uint32_t* pH, int kk) {
        #pragma unroll
        for (int np = 0; np < 8; np++) {
            uint32_t bv[4];
            ldsm4t(vbb + kk * 4352 + np * 32, bv);
            mma16816(O[2*np],   pH, bv[0], bv[1]);
            mma16816(O[2*np+1], pH, bv[2], bv[3]);
        }
    };

    const int nseg = half ? 1 : 2;
    for (int seg = 0; seg < nseg; seg++) {
        int qt, kbeg, kend, mode, slot;
        if (half == 0) {
            if (seg == 0) { qt = ip;      kbeg = 0;          kend = 2*ip + 2;  mode = 0; slot = 0; }
            else          { qt = 31 - ip; kbeg = 0;          kend = 31 - 2*ip; mode = 1; slot = 0; }
        } else            { qt = 31 - ip; kbeg = 31 - 2*ip;  kend = 64 - 2*ip; mode = 1; slot = 1; }
        const int q0 = qt * 128;
        const int n  = kend - kbeg;

        __syncthreads();   // prior segment done reading Q smem / all loads drained
        // ---- stage Q (single fp16, pre-scaled) + KV(kbeg) in one group ----
        #pragma unroll
        for (int i = 0; i < 8; i++) {
            int pid = t + i * 256;
            int row = pid >> 4, piece = pid & 15;
            cpa16(sb + FQ + row * 272 + piece * 16,
                  g_qh + ((size_t)b * SEQ + q0 + row) * DD + piece * 8);
        }
        {   // KV(kbeg) -> buffer 0, same commit group as Q
            const int k0 = kbeg * 64;
            const uint32_t bb = sb + FKV;
            #pragma unroll
            for (int i = 0; i < 8; i++) {
                int pid = t + i * 256;
                int arr = pid >> 10, r2 = pid & 1023;
                int row = r2 >> 4, piece = r2 & 15;
                const __half* src = (arr ? g_vh : g_kh)
                    + ((size_t)b * SEQ + k0 + row) * DD + piece * 8;
                cpa16(bb + arr * 17408 + row * 272 + piece * 16, src);
            }
            CP_COMMIT();
        }
        if (n >= 2) { issue_kv(1, kbeg + 1); CP_WAIT1(); }
        else        { CP_WAIT0(); }
        __syncthreads();   // Q + KV(kbeg) visible

        #pragma unroll
        for (int i = 0; i < 16; i++)
            #pragma unroll
            for (int j = 0; j < 4; j++) O[i][j] = 0.f;
        float lsA = 0.f, lsB = 0.f;

        // ---- prologue: QK for tile kbeg (buffer 0) ----
        #pragma unroll
        for (int ii = 0; ii < 8; ii++)
            #pragma unroll
            for (int j = 0; j < 4; j++) S[ii][j] = 0.f;
        #pragma unroll
        for (int ks = 0; ks < 8; ks++) qk_step(sb + FKV + kb_lane, ks);

        for (int i = 0; i < n; i++) {
            const int k0 = (kbeg + i) * 64;
            const bool hasnext = (i + 1 < n);
            if (hasnext) CP_WAIT0();   // KV(i+1) landed
            __syncthreads();           // all warps done with buf (i+2)%3's old data
            if (i + 2 < n) issue_kv((i + 2) % 3, kbeg + i + 2);

            // ---- softmax for tile i: p = exp2(s), causal mask, pack fp16 ----
            const int rA = q0 + 16 * w + g;
            const int rB = rA + 8;
            const bool diag = (k0 + 63 > q0);
            uint32_t ph[16];
            #pragma unroll
            for (int nt = 0; nt < 8; nt++) {
                int nn = k0 + 8 * nt + 2 * tig;
                float e0 = ex2(S[nt][0]);
                float e1 = ex2(S[nt][1]);
                float e2 = ex2(S[nt][2]);
                float e3 = ex2(S[nt][3]);
                if (diag) {
                    if (nn     > rA) e0 = 0.f;
                    if (nn + 1 > rA) e1 = 0.f;
                    if (nn     > rB) e2 = 0.f;
                    if (nn + 1 > rB) e3 = 0.f;
                }
                lsA += e0 + e1;
                lsB += e2 + e3;
                ph[2*nt]     = pack2h(e0, e1);
                ph[2*nt + 1] = pack2h(e2, e3);
            }

            // ---- PV(i) interleaved with QK(i+1), barrier-free ----
            const uint32_t vbb = sb + FKV + (uint32_t)((i % 3) * KVBUF)
                               + 17408 + vb_lane;
            if (hasnext) {
                const uint32_t kbn = sb + FKV
                                   + (uint32_t)(((i + 1) % 3) * KVBUF) + kb_lane;
                #pragma unroll
                for (int ii = 0; ii < 8; ii++)
                    #pragma unroll
                    for (int j = 0; j < 4; j++) S[ii][j] = 0.f;
                #pragma unroll
                for (int kk = 0; kk < 4; kk++) {
                    pv_step(vbb, &ph[4 * kk], kk);
                    qk_step(kbn, 2 * kk);
                    qk_step(kbn, 2 * kk + 1);
                }
            } else {
                #pragma unroll
                for (int kk = 0; kk < 4; kk++) pv_step(vbb, &ph[4 * kk], kk);
            }
        }

        // ---- reduce row sums across the 4-thread quad ----
        lsA += __shfl_xor_sync(0xffffffffu, lsA, 1);
        lsA += __shfl_xor_sync(0xffffffffu, lsA, 2);
        lsB += __shfl_xor_sync(0xffffffffu, lsB, 1);
        lsB += __shfl_xor_sync(0xffffffffu, lsB, 2);

        // ---- epilogue (direct from registers) ----
        const int rowA = q0 + 16 * w + g;
        if (mode == 0) {
            float iA = 1.f / lsA, iB = 1.f / lsB;
            float* oA = out + ((size_t)b * SEQ + rowA) * DD;
            float* oB = oA + 8 * DD;
            #pragma unroll
            for (int nt = 0; nt < 16; nt++) {
                int col = 8 * nt + 2 * tig;
                *reinterpret_cast<float2*>(&oA[col]) =
                    make_float2(O[nt][0] * iA, O[nt][1] * iA);
                *reinterpret_cast<float2*>(&oB[col]) =
                    make_float2(O[nt][2] * iB, O[nt][3] * iB);
            }
        } else {
            const int pbase = ((b * 16 + ip) * 2 + slot) * 128;
            float* pA = g_Opart + ((size_t)pbase + 16 * w + g) * 128;
            float* pB = pA + 8 * 128;
            #pragma unroll
            for (int nt = 0; nt < 16; nt++) {
                int col = 8 * nt + 2 * tig;
                *reinterpret_cast<float2*>(&pA[col]) = make_float2(O[nt][0], O[nt][1]);
                *reinterpret_cast<float2*>(&pB[col]) = make_float2(O[nt][2], O[nt][3]);
            }
            if (tig == 0) {
                g_lpart[pbase + 16 * w + g]     = lsA;
                g_lpart[pbase + 16 * w + g + 8] = lsB;
            }
        }
    }
}

// ===========================================================================
// Kernel 3: merge split-KV partials for q-tiles 16..31.
// ===========================================================================
__global__ __launch_bounds__(128) void merge_kernel(float* __restrict__ out)
{
    const int b  = blockIdx.x >> 4;
    const int ip = blockIdx.x & 15;
    const int qt = 31 - ip;
    const int r  = threadIdx.x;

    const size_t base0 = ((size_t)(((b * 16 + ip) * 2 + 0) * 128 + r)) * 128;
    const size_t base1 = base0 + 128 * 128;
    const float lsum = g_lpart[(((b * 16 + ip) * 2 + 0) * 128) + r]
                     + g_lpart[(((b * 16 + ip) * 2 + 1) * 128) + r];
    const float inv = 1.f / lsum;
    float* orow = &out[((size_t)b * SEQ + qt * 128 + r) * DD];
    #pragma unroll 8
    for (int d = 0; d < 128; d += 4) {
        float4 a = *reinterpret_cast<const float4*>(&g_Opart[base0 + d]);
        float4 c = *reinterpret_cast<const float4*>(&g_Opart[base1 + d]);
        float4 o = {(a.x + c.x) * inv, (a.y + c.y) * inv,
                    (a.z + c.z) * inv, (a.w + c.w) * inv};
        *reinterpret_cast<float4*>(&orow[d]) = o;
    }
}

// ---------------------------------------------------------------------------
extern "C" void kernel_launch(void* const* d_in, const int* in_sizes, int n_in,
                              void* d_out, int out_size)
{
    (void)in_sizes; (void)n_in; (void)out_size;
    const float* x  = (const float*)d_in[0];
    const float* Wq = (const float*)d_in[1];
    const float* Wk = (const float*)d_in[2];
    const float* Wv = (const float*)d_in[3];
    float* out = (float*)d_out;

    conv_x_kernel<<<(size_t)BS * EMB / 2048, 256>>>(x);
    conv_w_kernel<<<dim3(EMB * DD / 1024, 3), 256>>>(Wq, Wk, Wv);

    cudaFuncSetAttribute(qkv_gemm,
                         cudaFuncAttributeMaxDynamicSharedMemorySize, G_SMEM);
    qkv_gemm<<<dim3(128, 3), 256, G_SMEM>>>();

    cudaFuncSetAttribute(flash_attn,
                         cudaFuncAttributeMaxDynamicSharedMemorySize, FA_SMEM);
    flash_attn<<<128, 256, FA_SMEM>>>(out);

    merge_kernel<<<64, 128>>>(out);
}

// round 13
// speedup vs baseline: 1.2347x; 1.2347x over previous
#include <cuda_runtime.h>
#include <cuda_fp16.h>
#include <cstdint>

#define BATCH 4
#define SEQ   4096
#define EMB   1024
#define DD    128
#define BS    (BATCH * SEQ)

// Scratch (allocation-free rule: __device__ globals).
__device__ __half g_xh[(size_t)BS * EMB];
__device__ __half g_wh[3 * EMB * DD];
__device__ __half g_qh[(size_t)BS * DD];   // pre-scaled by qsc (fp16)
__device__ __half g_kh[(size_t)BS * DD];
__device__ __half g_vh[(size_t)BS * DD];
// Split-KV partials: [batch 4][pair 16][slot 2][row 128][d 128] and l.
__device__ float g_Opart[4 * 16 * 2 * 128 * 128];
__device__ float g_lpart[4 * 16 * 2 * 128];

// ===========================================================================
// Helpers — baseline sm_100 PTX (ldmatrix + mma.sync fp16 + cp.async).
// ===========================================================================
__device__ __forceinline__ uint32_t smem_u32(const void* p) {
    uint32_t a;
    asm("{ .reg .u64 t; cvta.to.shared.u64 t, %1; cvt.u32.u64 %0, t; }"
        : "=r"(a) : "l"(p));
    return a;
}
// pack two fp32 -> f16x2 (first arg -> low half)
__device__ __forceinline__ uint32_t pack2h(float lo, float hi) {
    uint32_t r;
    asm("cvt.rn.f16x2.f32 %0, %1, %2;" : "=r"(r) : "f"(hi), "f"(lo));
    return r;
}
__device__ __forceinline__ float ex2(float x) {
    float r; asm("ex2.approx.f32 %0, %1;" : "=f"(r) : "f"(x)); return r;
}
__device__ __forceinline__ void cpa16(uint32_t dst, const void* src) {
    asm volatile("cp.async.cg.shared.global [%0], [%1], 16;"
        :: "r"(dst), "l"(__cvta_generic_to_global(src)) : "memory");
}
#define CP_COMMIT() asm volatile("cp.async.commit_group;" ::: "memory")
#define CP_WAIT1()  asm volatile("cp.async.wait_group 1;" ::: "memory")
#define CP_WAIT0()  asm volatile("cp.async.wait_group 0;" ::: "memory")

__device__ __forceinline__ void ldsm4(uint32_t a, uint32_t* r) {
    asm volatile("ldmatrix.sync.aligned.m8n8.x4.shared.b16 {%0,%1,%2,%3}, [%4];"
        : "=r"(r[0]), "=r"(r[1]), "=r"(r[2]), "=r"(r[3]) : "r"(a));
}
__device__ __forceinline__ void ldsm4t(uint32_t a, uint32_t* r) {
    asm volatile("ldmatrix.sync.aligned.m8n8.x4.trans.shared.b16 {%0,%1,%2,%3}, [%4];"
        : "=r"(r[0]), "=r"(r[1]), "=r"(r[2]), "=r"(r[3]) : "r"(a));
}
// D += A * B  (m16n8k16, fp16 -> f32)
__device__ __forceinline__ void mma16816(float* c, const uint32_t* a,
                                         uint32_t b0, uint32_t b1) {
    asm volatile(
        "mma.sync.aligned.m16n8k16.row.col.f32.f16.f16.f32 "
        "{%0,%1,%2,%3}, {%4,%5,%6,%7}, {%8,%9}, {%0,%1,%2,%3};"
        : "+f"(c[0]), "+f"(c[1]), "+f"(c[2]), "+f"(c[3])
        : "r"(a[0]), "r"(a[1]), "r"(a[2]), "r"(a[3]), "r"(b0), "r"(b1));
}

// ===========================================================================
// Kernel 0a: convert x (fp32) -> xh (fp16 single).  8 elems/thread.
// ===========================================================================
__global__ __launch_bounds__(256) void conv_x_kernel(const float* __restrict__ x)
{
    size_t i = ((size_t)blockIdx.x * 256 + threadIdx.x) * 8;
    float4 a = *reinterpret_cast<const float4*>(x + i);
    float4 b = *reinterpret_cast<const float4*>(x + i + 4);
    uint32_t h0 = pack2h(a.x, a.y), h1 = pack2h(a.z, a.w);
    uint32_t h2 = pack2h(b.x, b.y), h3 = pack2h(b.z, b.w);
    *reinterpret_cast<uint4*>(&g_xh[i]) = make_uint4(h0, h1, h2, h3);
}

// ===========================================================================
// Kernel 0b: convert Wq/Wk/Wv (fp32) -> wh (fp16 single).  4 elems/thread.
// ===========================================================================
__global__ __launch_bounds__(256) void conv_w_kernel(
    const float* __restrict__ Wq, const float* __restrict__ Wk,
    const float* __restrict__ Wv)
{
    const float* W = (blockIdx.y == 0) ? Wq : (blockIdx.y == 1) ? Wk : Wv;
    size_t i = ((size_t)blockIdx.x * 256 + threadIdx.x) * 4;
    float4 v = *reinterpret_cast<const float4*>(W + i);
    uint32_t p0 = pack2h(v.x, v.y), p1 = pack2h(v.z, v.w);
    *reinterpret_cast<uint2*>(&g_wh[(size_t)blockIdx.y * EMB * DD + i]) =
        make_uint2(p0, p1);
}

// ===========================================================================
// Kernel 1: QKV projection GEMM, SINGLE-TERM fp16 (Xh*Wh), cp.async 2-stage.
// Block 256 thr, tile M=128 N=128, K chunks of 64.  Warp tile 32M x 64N.
// grid = (128, 3).  Writes fp16 outputs (Q pre-scaled, single fp16).
// ===========================================================================
// per stage: X [128][144B] = 18432, W [64][272B] = 17408
#define GEM_BUF 35840
#define G_SMEM  (2 * GEM_BUF)    // 71680

__global__ __launch_bounds__(256, 2) void qkv_gemm(void)
{
    extern __shared__ char smem[];
    const uint32_t sb = smem_u32(smem);
    const int t = threadIdx.x;
    const int w = t >> 5, l = t & 31;
    const int g = l >> 2, tig = l & 3;
    const int wM = w & 3, wN = w >> 2;
    const int m0 = blockIdx.x * 128;
    const int y  = blockIdx.y;
    const __half* ws = g_wh + (size_t)y * EMB * DD;

    float C[2][8][4];
    #pragma unroll
    for (int m = 0; m < 2; m++)
        #pragma unroll
        for (int i = 0; i < 8; i++)
            #pragma unroll
            for (int j = 0; j < 4; j++) C[m][i][j] = 0.f;

    auto issue = [&](int p, int cc) {
        const uint32_t bb = sb + p * GEM_BUF;
        const int k0 = cc * 64;
        // X chunk [128 rows][64 k] fp16 = 8 x 16B pieces per row
        #pragma unroll
        for (int i = 0; i < 4; i++) {
            int pid = t + i * 256;
            int row = pid >> 3, piece = pid & 7;
            cpa16(bb + row * 144 + piece * 16,
                  g_xh + (size_t)(m0 + row) * EMB + k0 + piece * 8);
        }
        // W chunk [64 k][128 n] fp16 = 16 x 16B pieces per row
        #pragma unroll
        for (int i = 0; i < 4; i++) {
            int pid = t + i * 256;
            int row = pid >> 4, piece = pid & 15;
            cpa16(bb + 18432 + row * 272 + piece * 16,
                  ws + (size_t)(k0 + row) * DD + piece * 8);
        }
        CP_COMMIT();
    };

    issue(0, 0);
    issue(1, 1);

    const uint32_t xa_l = (uint32_t)(wM * 32 * 144
                        + (l & 15) * 144 + ((l >> 4) << 3) * 2);
    const uint32_t wb_l = (uint32_t)(((l & 7) + (l & 8)) * 272
                        + ((l >> 4) << 3) * 2 + wN * 128);

    for (int cc = 0; cc < 16; cc++) {
        const int p = cc & 1;
        if (cc < 15) CP_WAIT1(); else CP_WAIT0();
        __syncthreads();
        const uint32_t bb = sb + p * GEM_BUF;

        #pragma unroll
        for (int ks = 0; ks < 4; ks++) {
            uint32_t ah0[4], ah1[4];
            uint32_t xa = bb + xa_l + ks * 32;
            ldsm4(xa,            ah0);
            ldsm4(xa + 16 * 144, ah1);
            #pragma unroll
            for (int np = 0; np < 4; np++) {
                uint32_t bf[4];
                ldsm4t(bb + 18432 + wb_l + ks * 4352 + np * 32, bf);
                mma16816(C[0][2*np],   ah0, bf[0], bf[1]);
                mma16816(C[0][2*np+1], ah0, bf[2], bf[3]);
                mma16816(C[1][2*np],   ah1, bf[0], bf[1]);
                mma16816(C[1][2*np+1], ah1, bf[2], bf[3]);
            }
        }
        __syncthreads();
        if (cc + 2 < 16) issue(p, cc + 2);
    }

    // epilogue -> fp16 global (Q pre-scaled, single fp16)
    const float qsc = 0.08838834764831845f * 1.4426950408889634f;
    #pragma unroll
    for (int m = 0; m < 2; m++) {
        const int r0 = m0 + wM * 32 + m * 16 + g;
        const int r1 = r0 + 8;
        #pragma unroll
        for (int nt = 0; nt < 8; nt++) {
            const int col = wN * 64 + nt * 8 + 2 * tig;
            float v00 = C[m][nt][0], v01 = C[m][nt][1];
            float v10 = C[m][nt][2], v11 = C[m][nt][3];
            __half* dst;
            if (y == 0) {
                v00 *= qsc; v01 *= qsc; v10 *= qsc; v11 *= qsc;
                dst = g_qh;
            } else dst = (y == 1) ? g_kh : g_vh;
            *reinterpret_cast<uint32_t*>(&dst[(size_t)r0 * DD + col]) =
                pack2h(v00, v01);
            *reinterpret_cast<uint32_t*>(&dst[(size_t)r1 * DD + col]) =
                pack2h(v10, v11);
        }
    }
}

// ===========================================================================
// Kernel 2: causal flash attention — R11-passing version verbatim (256 thr,
// 8 warps, block-wide syncs, single-term fp16 MMAs, 2-stage KV ring,
// no-max softmax, O in fp32 regs, direct register epilogue).
// Schedule: pair ip -> 2 blocks of 33 units; grid 128.
// ===========================================================================
#define FQ      0
#define FKV     34816
#define KVBUF   34816
#define FA_SMEM (FKV + 2 * KVBUF)   // 104448

__global__ __launch_bounds__(256, 1) void flash_attn(float* __restrict__ out)
{
    extern __shared__ char smem[];
    const uint32_t sb = smem_u32(smem);
    const int t = threadIdx.x;
    const int w = t >> 5, l = t & 31;
    const int g = l >> 2, tig = l & 3;

    const int bid  = blockIdx.x;
    const int b    = bid >> 5;
    const int rem  = bid & 31;
    const int ip   = rem >> 1;
    const int half = rem & 1;

    const uint32_t qa_lane = (uint32_t)((16 * w + (l & 15)) * 272 + ((l >> 4) << 3) * 2);
    const uint32_t kb_lane = (uint32_t)(((l & 7) + ((l >> 4) << 3)) * 272 + (l & 8) * 2);
    const uint32_t vb_lane = (uint32_t)(((l & 7) + (l & 8)) * 272 + ((l >> 4) << 3) * 2);

    auto issue_kv = [&](int p, int kt) {
        const int k0 = kt * 64;
        const uint32_t bb = sb + FKV + (uint32_t)p * KVBUF;
        #pragma unroll
        for (int i = 0; i < 8; i++) {
            int pid = t + i * 256;
            int arr = pid >> 10, r2 = pid & 1023;
            int row = r2 >> 4, piece = r2 & 15;
            const __half* src = (arr ? g_vh : g_kh)
                + ((size_t)b * SEQ + k0 + row) * DD + piece * 8;
            cpa16(bb + arr * 17408 + row * 272 + piece * 16, src);
        }
        CP_COMMIT();
    };

    const int nseg = half ? 1 : 2;
    for (int seg = 0; seg < nseg; seg++) {
        int qt, kbeg, kend, mode, slot;
        if (half == 0) {
            if (seg == 0) { qt = ip;      kbeg = 0;          kend = 2*ip + 2;  mode = 0; slot = 0; }
            else          { qt = 31 - ip; kbeg = 0;          kend = 31 - 2*ip; mode = 1; slot = 0; }
        } else            { qt = 31 - ip; kbeg = 31 - 2*ip;  kend = 64 - 2*ip; mode = 1; slot = 1; }
        const int q0 = qt * 128;

        __syncthreads();   // prior segment done reading Q smem
        // ---- stage Q (single fp16, pre-scaled) + first KV in one group ----
        #pragma unroll
        for (int i = 0; i < 8; i++) {
            int pid = t + i * 256;
            int row = pid >> 4, piece = pid & 15;
            cpa16(sb + FQ + row * 272 + piece * 16,
                  g_qh + ((size_t)b * SEQ + q0 + row) * DD + piece * 8);
        }
        {   // KV(kbeg) shares this first group
            const int k0 = kbeg * 64;
            const uint32_t bb = sb + FKV;
            #pragma unroll
            for (int i = 0; i < 8; i++) {
                int pid = t + i * 256;
                int arr = pid >> 10, r2 = pid & 1023;
                int row = r2 >> 4, piece = r2 & 15;
                const __half* src = (arr ? g_vh : g_kh)
                    + ((size_t)b * SEQ + k0 + row) * DD + piece * 8;
                cpa16(bb + arr * 17408 + row * 272 + piece * 16, src);
            }
            CP_COMMIT();
        }
        if (kbeg + 1 < kend) issue_kv(1, kbeg + 1);

        float O[16][4];
        #pragma unroll
        for (int i = 0; i < 16; i++)
            #pragma unroll
            for (int j = 0; j < 4; j++) O[i][j] = 0.f;
        float lsA = 0.f, lsB = 0.f;

        for (int kt = kbeg; kt < kend; kt++) {
            if (kt + 1 < kend) CP_WAIT1(); else CP_WAIT0();
            __syncthreads();
            const int p  = (kt - kbeg) & 1;
            const int k0 = kt * 64;
            const uint32_t kb = sb + FKV + (uint32_t)p * KVBUF + kb_lane;
            const uint32_t vb = sb + FKV + (uint32_t)p * KVBUF + 17408 + vb_lane;

            // ---- S = Q K^T (single-term) ----
            float S[8][4];
            #pragma unroll
            for (int i = 0; i < 8; i++)
                #pragma unroll
                for (int j = 0; j < 4; j++) S[i][j] = 0.f;

            #pragma unroll
            for (int ks = 0; ks < 8; ks++) {
                uint32_t ah[4];
                ldsm4(sb + FQ + qa_lane + ks * 32, ah);
                #pragma unroll
                for (int np = 0; np < 4; np++) {
                    uint32_t bk[4];
                    ldsm4(kb + np * 4352 + ks * 32, bk);
                    mma16816(S[2*np],   ah, bk[0], bk[1]);
                    mma16816(S[2*np+1], ah, bk[2], bk[3]);
                }
            }

            // ---- softmax: p = exp2(s), causal mask, pack fp16 ----
            const int rA = q0 + 16 * w + g;
            const int rB = rA + 8;
            const bool diag = (k0 + 63 > q0);
            uint32_t ph[16];
            #pragma unroll
            for (int nt = 0; nt < 8; nt++) {
                int n = k0 + 8 * nt + 2 * tig;
                float e0 = ex2(S[nt][0]);
                float e1 = ex2(S[nt][1]);
                float e2 = ex2(S[nt][2]);
                float e3 = ex2(S[nt][3]);
                if (diag) {
                    if (n     > rA) e0 = 0.f;
                    if (n + 1 > rA) e1 = 0.f;
                    if (n     > rB) e2 = 0.f;
                    if (n + 1 > rB) e3 = 0.f;
                }
                lsA += e0 + e1;
                lsB += e2 + e3;
                ph[2*nt]     = pack2h(e0, e1);
                ph[2*nt + 1] = pack2h(e2, e3);
            }

            // ---- O += P V (single-term) ----
            #pragma unroll
            for (int kk = 0; kk < 4; kk++) {
                const uint32_t* pH = &ph[4 * kk];
                #pragma unroll
                for (int np = 0; np < 8; np++) {
                    uint32_t bv[4];
                    ldsm4t(vb + kk * 4352 + np * 32, bv);
                    mma16816(O[2*np],   pH, bv[0], bv[1]);
                    mma16816(O[2*np+1], pH, bv[2], bv[3]);
                }
            }
            __syncthreads();
            if (kt + 2 < kend) issue_kv(p, kt + 2);
        }

        // ---- reduce row sums across the 4-thread quad ----
        lsA += __shfl_xor_sync(0xffffffffu, lsA, 1);
        lsA += __shfl_xor_sync(0xffffffffu, lsA, 2);
        lsB += __shfl_xor_sync(0xffffffffu, lsB, 1);
        lsB += __shfl_xor_sync(0xffffffffu, lsB, 2);

        // ---- epilogue (direct from registers) ----
        const int rowA = q0 + 16 * w + g;
        if (mode == 0) {
            float iA = 1.f / lsA, iB = 1.f / lsB;
            float* oA = out + ((size_t)b * SEQ + rowA) * DD;
            float* oB = oA + 8 * DD;
            #pragma unroll
            for (int nt = 0; nt < 16; nt++) {
                int col = 8 * nt + 2 * tig;
                *reinterpret_cast<float2*>(&oA[col]) =
                    make_float2(O[nt][0] * iA, O[nt][1] * iA);
                *reinterpret_cast<float2*>(&oB[col]) =
                    make_float2(O[nt][2] * iB, O[nt][3] * iB);
            }
        } else {
            const int pbase = ((b * 16 + ip) * 2 + slot) * 128;
            float* pA = g_Opart + ((size_t)pbase + 16 * w + g) * 128;
            float* pB = pA + 8 * 128;
            #pragma unroll
            for (int nt = 0; nt < 16; nt++) {
                int col = 8 * nt + 2 * tig;
                *reinterpret_cast<float2*>(&pA[col]) = make_float2(O[nt][0], O[nt][1]);
                *reinterpret_cast<float2*>(&pB[col]) = make_float2(O[nt][2], O[nt][3]);
            }
            if (tig == 0) {
                g_lpart[pbase + 16 * w + g]     = lsA;
                g_lpart[pbase + 16 * w + g + 8] = lsB;
            }
        }
    }
}

// ===========================================================================
// Kernel 3: merge split-KV partials for q-tiles 16..31.  512 thr/block:
// thread -> (row t>>2, 32-col strip (t&3)*32).
// ===========================================================================
__global__ __launch_bounds__(512) void merge_kernel(float* __restrict__ out)
{
    const int b  = blockIdx.x >> 4;
    const int ip = blockIdx.x & 15;
    const int qt = 31 - ip;
    const int r  = threadIdx.x >> 2;
    const int c0 = (threadIdx.x & 3) * 32;

    const size_t base0 = ((size_t)(((b * 16 + ip) * 2 + 0) * 128 + r)) * 128;
    const size_t base1 = base0 + 128 * 128;
    const float lsum = g_lpart[(((b * 16 + ip) * 2 + 0) * 128) + r]
                     + g_lpart[(((b * 16 + ip) * 2 + 1) * 128) + r];
    const float inv = 1.f / lsum;
    float* orow = &out[((size_t)b * SEQ + qt * 128 + r) * DD];
    #pragma unroll
    for (int j = 0; j < 8; j++) {
        int d = c0 + 4 * j;
        float4 a = *reinterpret_cast<const float4*>(&g_Opart[base0 + d]);
        float4 c = *reinterpret_cast<const float4*>(&g_Opart[base1 + d]);
        float4 o = {(a.x + c.x) * inv, (a.y + c.y) * inv,
                    (a.z + c.z) * inv, (a.w + c.w) * inv};
        *reinterpret_cast<float4*>(&orow[d]) = o;
    }
}

// ---------------------------------------------------------------------------
extern "C" void kernel_launch(void* const* d_in, const int* in_sizes, int n_in,
                              void* d_out, int out_size)
{
    (void)in_sizes; (void)n_in; (void)out_size;
    const float* x  = (const float*)d_in[0];
    const float* Wq = (const float*)d_in[1];
    const float* Wk = (const float*)d_in[2];
    const float* Wv = (const float*)d_in[3];
    float* out = (float*)d_out;

    conv_x_kernel<<<(size_t)BS * EMB / 2048, 256>>>(x);
    conv_w_kernel<<<dim3(EMB * DD / 1024, 3), 256>>>(Wq, Wk, Wv);

    cudaFuncSetAttribute(qkv_gemm,
                         cudaFuncAttributeMaxDynamicSharedMemorySize, G_SMEM);
    qkv_gemm<<<dim3(128, 3), 256, G_SMEM>>>();

    cudaFuncSetAttribute(flash_attn,
                         cudaFuncAttributeMaxDynamicSharedMemorySize, FA_SMEM);
    flash_attn<<<128, 256, FA_SMEM>>>(out);

    merge_kernel<<<64, 512>>>(out);
}